// round 2
// baseline (speedup 1.0000x reference)
#include <cuda_runtime.h>
#include <math.h>

// Problem constants
#define BB   8
#define SPT  32768          // 32*32*32
#define NHEADS 8

// ---------------- scratch (device globals: allocation-free) ----------------
__device__ float g_qkv_pre[(size_t)BB * 192 * SPT];   // 192 MiB
__device__ float g_v[(size_t)BB * 64 * SPT];          //  64 MiB
__device__ float g_partials[BB * NHEADS * 16 * 80];   // per-tile gram/norm partials
__device__ float g_M[BB * 64 * 64];                   // folded attn+proj matrices

// ---------------------------------------------------------------------------
// GEMM: C[b][oc][s] = A[oc][k=64] * X[b][k][s].  OC tile 64, S tile 256,
// 256 threads, 8x8 register tile per thread.  APB: A is per-batch (K4) or
// shared (K1).
// ---------------------------------------------------------------------------
template<bool APB>
__global__ __launch_bounds__(256, 2)
void gemm_kernel(const float* __restrict__ A,
                 const float* __restrict__ X,
                 float* __restrict__ C, int OCtot)
{
    extern __shared__ float sm[];
    float* As = sm;            // [64][64]
    float4* Xs4 = (float4*)(sm + 4096);  // [64][64] float4 = [64][256] floats

    const int tid = threadIdx.x;
    const int b   = blockIdx.z;
    const int s0  = blockIdx.y * 256;
    const int ocb = blockIdx.x * 64;

    const float* Ab = A + (APB ? (size_t)b * OCtot * 64 : (size_t)0) + (size_t)ocb * 64;
    for (int i = tid; i < 4096; i += 256) As[i] = Ab[i];

    const float* Xb = X + (size_t)b * 64 * SPT + s0;
    for (int i = tid; i < 4096; i += 256) {
        int row = i >> 6, c4 = i & 63;
        Xs4[i] = ((const float4*)(Xb + (size_t)row * SPT))[c4];
    }
    __syncthreads();

    const int warp = tid >> 5, lane = tid & 31;
    float acc[8][8];
    #pragma unroll
    for (int i = 0; i < 8; i++)
        #pragma unroll
        for (int j = 0; j < 8; j++) acc[i][j] = 0.f;

    #pragma unroll 4
    for (int k = 0; k < 64; k++) {
        float a[8];
        #pragma unroll
        for (int i = 0; i < 8; i++) a[i] = As[(warp * 8 + i) * 64 + k];
        float4 x0 = Xs4[k * 64 + lane * 2];
        float4 x1 = Xs4[k * 64 + lane * 2 + 1];
        float xv[8] = {x0.x, x0.y, x0.z, x0.w, x1.x, x1.y, x1.z, x1.w};
        #pragma unroll
        for (int i = 0; i < 8; i++)
            #pragma unroll
            for (int j = 0; j < 8; j++)
                acc[i][j] = fmaf(a[i], xv[j], acc[i][j]);
    }

    #pragma unroll
    for (int i = 0; i < 8; i++) {
        float* Crow = C + ((size_t)b * OCtot + ocb + warp * 8 + i) * SPT + s0 + lane * 8;
        ((float4*)Crow)[0] = make_float4(acc[i][0], acc[i][1], acc[i][2], acc[i][3]);
        ((float4*)Crow)[1] = make_float4(acc[i][4], acc[i][5], acc[i][6], acc[i][7]);
    }
}

// ---------------------------------------------------------------------------
// Depthwise 3x3x3 conv + fused gram/norm partials + v store.
// Block: (b, head, 8x8x32 spatial tile).  Per head: 8 k channels computed and
// cached in smem, 8 v channels written to g_v, 8 q channels streamed against
// cached k to form gram partials.  All reductions fixed-order (deterministic).
// ---------------------------------------------------------------------------
__global__ __launch_bounds__(256, 2)
void dw_kernel(const float* __restrict__ w_dw)
{
    extern __shared__ float sm[];
    float* halo  = sm;               // 10*10*34 = 3400
    float* ks    = sm + 3400;        // 8*2048  = 16384
    float* gacc  = ks + 16384;       // 64
    float* qnacc = gacc + 64;        // 8
    float* knacc = qnacc + 8;        // 8
    float* wds   = knacc + 8;        // 28 (27 used)
    float* wpart = wds + 28;         // 8 warps * 9 slots = 72
    // total 19964 floats

    const int tid = threadIdx.x;
    const int b = blockIdx.z, h = blockIdx.y;
    const int z0 = (blockIdx.x >> 2) * 8;
    const int y0 = (blockIdx.x & 3) * 8;
    const int ly = tid >> 5, lx = tid & 31;
    const int warp = ly, lane = lx;

    if (tid < 64) gacc[tid] = 0.f;
    else if (tid < 72) qnacc[tid - 64] = 0.f;
    else if (tid < 80) knacc[tid - 72] = 0.f;

    for (int phase = 0; phase < 3; phase++) {        // 0=k, 1=v, 2=q
        for (int cl = 0; cl < 8; cl++) {
            const int gch = (phase == 0 ? 64 : phase == 1 ? 128 : 0) + h * 8 + cl;

            if (tid < 27) wds[tid] = w_dw[gch * 27 + tid];

            const float* src = g_qkv_pre + ((size_t)(b * 192 + gch)) * SPT;
            for (int idx = tid; idx < 3400; idx += 256) {
                int hz = idx / 340, r = idx - hz * 340;
                int hy = r / 34,   hx = r - hy * 34;
                int gz = z0 - 1 + hz, gy = y0 - 1 + hy, gx = hx - 1;
                float v = 0.f;
                if ((unsigned)gz < 32u && (unsigned)gy < 32u && (unsigned)gx < 32u)
                    v = src[gz * 1024 + gy * 32 + gx];
                halo[idx] = v;
            }
            __syncthreads();

            float wr[27];
            #pragma unroll
            for (int t = 0; t < 27; t++) wr[t] = wds[t];

            float pa[9], pb[9], pc[9];
            #pragma unroll
            for (int e = 0; e < 9; e++) {
                int dy = e / 3, dx = e % 3;
                pa[e] = halo[0 * 340 + (ly + dy) * 34 + lx + dx];
                pb[e] = halo[1 * 340 + (ly + dy) * 34 + lx + dx];
            }

            float qn_l = 0.f, kn_l = 0.f, gl[8];
            #pragma unroll
            for (int d = 0; d < 8; d++) gl[d] = 0.f;

            #pragma unroll
            for (int lz = 0; lz < 8; lz++) {
                #pragma unroll
                for (int e = 0; e < 9; e++) {
                    int dy = e / 3, dx = e % 3;
                    pc[e] = halo[(lz + 2) * 340 + (ly + dy) * 34 + lx + dx];
                }
                float val = 0.f;
                #pragma unroll
                for (int e = 0; e < 9; e++) val = fmaf(wr[e],      pa[e], val);
                #pragma unroll
                for (int e = 0; e < 9; e++) val = fmaf(wr[9 + e],  pb[e], val);
                #pragma unroll
                for (int e = 0; e < 9; e++) val = fmaf(wr[18 + e], pc[e], val);

                const int p = lz * 256 + tid;
                if (phase == 0) {
                    ks[cl * 2048 + p] = val;
                    kn_l = fmaf(val, val, kn_l);
                } else if (phase == 1) {
                    g_v[((size_t)(b * 64 + h * 8 + cl)) * SPT
                        + (z0 + lz) * 1024 + (y0 + ly) * 32 + lx] = val;
                } else {
                    qn_l = fmaf(val, val, qn_l);
                    #pragma unroll
                    for (int d = 0; d < 8; d++)
                        gl[d] = fmaf(val, ks[d * 2048 + p], gl[d]);
                }
                #pragma unroll
                for (int e = 0; e < 9; e++) { pa[e] = pb[e]; pb[e] = pc[e]; }
            }

            // deterministic warp-level reductions into wpart
            if (phase == 0) {
                #pragma unroll
                for (int o = 16; o; o >>= 1) kn_l += __shfl_xor_sync(0xffffffffu, kn_l, o);
                if (lane == 0) wpart[warp * 9] = kn_l;
            } else if (phase == 2) {
                #pragma unroll
                for (int d = 0; d < 8; d++) {
                    float v = gl[d];
                    #pragma unroll
                    for (int o = 16; o; o >>= 1) v += __shfl_xor_sync(0xffffffffu, v, o);
                    if (lane == 0) wpart[warp * 9 + d] = v;
                }
                #pragma unroll
                for (int o = 16; o; o >>= 1) qn_l += __shfl_xor_sync(0xffffffffu, qn_l, o);
                if (lane == 0) wpart[warp * 9 + 8] = qn_l;
            }
            __syncthreads();

            // fixed-order cross-warp accumulation (single thread per slot)
            if (phase == 0) {
                if (tid == 0) {
                    float s = 0.f;
                    #pragma unroll
                    for (int w = 0; w < 8; w++) s += wpart[w * 9];
                    knacc[cl] += s;
                }
            } else if (phase == 2) {
                if (tid < 9) {
                    float s = 0.f;
                    #pragma unroll
                    for (int w = 0; w < 8; w++) s += wpart[w * 9 + tid];
                    if (tid < 8) gacc[cl * 8 + tid] += s;
                    else         qnacc[cl] += s;
                }
            }
            // next channel's post-halo __syncthreads separates wpart reuse
        }
    }
    __syncthreads();
    if (tid < 80) {
        float v = tid < 64 ? gacc[tid] : tid < 72 ? qnacc[tid - 64] : knacc[tid - 72];
        g_partials[(((size_t)(b * 8 + h)) * 16 + blockIdx.x) * 80 + tid] = v;
    }
}

// ---------------------------------------------------------------------------
// Tiny kernel: reduce tile partials -> L2-normalized gram -> softmax -> fold
// with w_proj into M[b][o][h*8+d].
// ---------------------------------------------------------------------------
__global__ void attn_kernel(const float* __restrict__ temp,
                            const float* __restrict__ w_proj)
{
    __shared__ float stat_s[8][80];   // per head: 64 gram, 8 qn2, 8 kn2
    __shared__ float attn_s[8][8][8]; // [h][c][d]
    const int b = blockIdx.x, tid = threadIdx.x;

    for (int idx = tid; idx < 640; idx += 256) {
        int h = idx / 80, j = idx - h * 80;
        float s = 0.f;
        #pragma unroll
        for (int t = 0; t < 16; t++)
            s += g_partials[(((size_t)(b * 8 + h)) * 16 + t) * 80 + j];
        stat_s[h][j] = s;
    }
    __syncthreads();

    if (tid < 64) {
        const int h = tid >> 3, c = tid & 7;
        const float qn = fmaxf(sqrtf(stat_s[h][64 + c]), 1e-12f);
        const float tmp = temp[b];
        float g[8]; float mx = -1e30f;
        #pragma unroll
        for (int d = 0; d < 8; d++) {
            float kn = fmaxf(sqrtf(stat_s[h][72 + d]), 1e-12f);
            g[d] = stat_s[h][c * 8 + d] / (qn * kn) * tmp;
            mx = fmaxf(mx, g[d]);
        }
        float ssum = 0.f;
        #pragma unroll
        for (int d = 0; d < 8; d++) { g[d] = expf(g[d] - mx); ssum += g[d]; }
        const float inv = 1.f / ssum;
        #pragma unroll
        for (int d = 0; d < 8; d++) attn_s[h][c][d] = g[d] * inv;
    }
    __syncthreads();

    for (int e = tid; e < 4096; e += 256) {
        int o = e >> 6, j = e & 63, h = j >> 3, d = j & 7;
        float m = 0.f;
        #pragma unroll
        for (int c = 0; c < 8; c++)
            m = fmaf(w_proj[o * 64 + h * 8 + c], attn_s[h][c][d], m);
        g_M[b * 4096 + e] = m;
    }
}

// ---------------------------------------------------------------------------
extern "C" void kernel_launch(void* const* d_in, const int* in_sizes, int n_in,
                              void* d_out, int out_size)
{
    const float* x      = (const float*)d_in[0];
    const float* w_qkv  = (const float*)d_in[1];
    const float* w_dw   = (const float*)d_in[2];
    const float* w_proj = (const float*)d_in[3];
    const float* temp   = (const float*)d_in[4];
    float* out = (float*)d_out;

    void *p_qkv, *p_v, *p_M;
    cudaGetSymbolAddress(&p_qkv, g_qkv_pre);
    cudaGetSymbolAddress(&p_v,   g_v);
    cudaGetSymbolAddress(&p_M,   g_M);

    const int gemm_smem = (4096 + 16384) * 4;   // 80 KiB
    const int dw_smem   = 19964 * 4;            // ~78 KiB
    cudaFuncSetAttribute(gemm_kernel<false>, cudaFuncAttributeMaxDynamicSharedMemorySize, gemm_smem);
    cudaFuncSetAttribute(gemm_kernel<true>,  cudaFuncAttributeMaxDynamicSharedMemorySize, gemm_smem);
    cudaFuncSetAttribute(dw_kernel,          cudaFuncAttributeMaxDynamicSharedMemorySize, dw_smem);

    // K1: qkv pointwise conv (per-batch GEMM, A shared)
    gemm_kernel<false><<<dim3(3, 128, 8), 256, gemm_smem>>>(w_qkv, x, (float*)p_qkv, 192);
    // K2: depthwise conv + gram/norm partials + v
    dw_kernel<<<dim3(16, 8, 8), 256, dw_smem>>>(w_dw);
    // K3: softmax + fold attn with w_proj into per-batch 64x64 M
    attn_kernel<<<8, 256>>>(temp, w_proj);
    // K4: y = M * v, writes d_out (per-batch A)
    gemm_kernel<true><<<dim3(1, 128, 8), 256, gemm_smem>>>((const float*)p_M, (const float*)p_v, out, 64);
}

// round 3
// speedup vs baseline: 1.3750x; 1.3750x over previous
#include <cuda_runtime.h>
#include <math.h>

// Problem constants
#define BB   8
#define SPT  32768          // 32*32*32
#define NHEADS 8

// ---------------- scratch (device globals: allocation-free) ----------------
__device__ float g_qkv_pre[(size_t)BB * 192 * SPT];   // 192 MiB
__device__ float g_v[(size_t)BB * 64 * SPT];          //  64 MiB
__device__ float g_partials[BB * NHEADS * 16 * 80];   // per-tile gram/norm partials
__device__ float g_M[BB * 64 * 64];                   // folded attn+proj matrices

// ---------------------------------------------------------------------------
// GEMM: C[b][oc][s] = A[oc][k=64] * X[b][k][s].
// OC tile 64, S tile 128, 256 threads, 8x4 register tile per thread.
// smem = 48 KiB -> 4 CTAs/SM (regs capped at 64 via launch_bounds).
// ---------------------------------------------------------------------------
template<bool APB>
__global__ __launch_bounds__(256, 4)
void gemm_kernel(const float* __restrict__ A,
                 const float* __restrict__ X,
                 float* __restrict__ C, int OCtot)
{
    extern __shared__ float sm[];
    float*  As  = sm;                    // [64][64] = 16 KiB
    float4* Xs4 = (float4*)(sm + 4096);  // [64][32] float4 = 32 KiB

    const int tid = threadIdx.x;
    const int b   = blockIdx.z;
    const int s0  = blockIdx.y * 128;
    const int ocb = blockIdx.x * 64;

    const float* Ab = A + (APB ? (size_t)b * OCtot * 64 : (size_t)0) + (size_t)ocb * 64;
    {
        const float4* Ab4 = (const float4*)Ab;
        #pragma unroll
        for (int i = 0; i < 4; i++)
            ((float4*)As)[tid + i * 256] = Ab4[tid + i * 256];
    }
    const float* Xb = X + (size_t)b * 64 * SPT + s0;
    #pragma unroll
    for (int i = 0; i < 8; i++) {
        int e = tid + i * 256;           // 2048 float4s
        int row = e >> 5, c4 = e & 31;
        Xs4[e] = ((const float4*)(Xb + (size_t)row * SPT))[c4];
    }
    __syncthreads();

    const int warp = tid >> 5, lane = tid & 31;
    float acc[8][4];
    #pragma unroll
    for (int i = 0; i < 8; i++)
        #pragma unroll
        for (int j = 0; j < 4; j++) acc[i][j] = 0.f;

    #pragma unroll 4
    for (int k = 0; k < 64; k++) {
        float a[8];
        #pragma unroll
        for (int i = 0; i < 8; i++) a[i] = As[(warp * 8 + i) * 64 + k];  // broadcast
        float4 xv = Xs4[k * 32 + lane];
        #pragma unroll
        for (int i = 0; i < 8; i++) {
            acc[i][0] = fmaf(a[i], xv.x, acc[i][0]);
            acc[i][1] = fmaf(a[i], xv.y, acc[i][1]);
            acc[i][2] = fmaf(a[i], xv.z, acc[i][2]);
            acc[i][3] = fmaf(a[i], xv.w, acc[i][3]);
        }
    }

    #pragma unroll
    for (int i = 0; i < 8; i++) {
        float* Crow = C + ((size_t)b * OCtot + ocb + warp * 8 + i) * SPT + s0 + lane * 4;
        *((float4*)Crow) = make_float4(acc[i][0], acc[i][1], acc[i][2], acc[i][3]);
    }
}

// ---------------------------------------------------------------------------
// Depthwise 3x3x3 conv + fused gram/norm partials + v store.
// Double-buffered halo: step s prefetches step s+1's halo (reg-staged LDG,
// STS after compute) so global latency overlaps the conv FMA body.
// All reductions fixed-order (deterministic).
// ---------------------------------------------------------------------------
__global__ __launch_bounds__(256, 2)
void dw_kernel(const float* __restrict__ w_dw)
{
    extern __shared__ float sm[];
    float* halo  = sm;               // 2 * 3400
    float* ks    = sm + 6800;        // 8*2048 = 16384
    float* gacc  = ks + 16384;       // 64
    float* qnacc = gacc + 64;        // 8
    float* knacc = qnacc + 8;        // 8
    float* wall  = knacc + 8;        // 24*27 = 648
    float* wpart = wall + 648;       // 8 warps * 9 slots = 72
    // total 23984 floats = ~93.7 KiB

    const int tid = threadIdx.x;
    const int b = blockIdx.z, h = blockIdx.y;
    const int z0 = (blockIdx.x >> 2) * 8;
    const int y0 = (blockIdx.x & 3) * 8;
    const int ly = tid >> 5, lx = tid & 31;
    const int warp = ly, lane = lx;

    if (tid < 64) gacc[tid] = 0.f;
    else if (tid < 72) qnacc[tid - 64] = 0.f;
    else if (tid < 80) knacc[tid - 72] = 0.f;

    // preload all 24 channels' weights (step order: k ch 0-7, v 0-7, q 0-7)
    for (int i = tid; i < 648; i += 256) {
        int step = i / 27, t = i - step * 27;
        int phase = step >> 3, cl = step & 7;
        int gch = (phase == 0 ? 64 : phase == 1 ? 128 : 0) + h * 8 + cl;
        wall[i] = w_dw[gch * 27 + t];
    }

    // prologue: halo for step 0 (k channel 0)
    {
        const float* src = g_qkv_pre + ((size_t)(b * 192 + 64 + h * 8)) * SPT;
        for (int idx = tid; idx < 3400; idx += 256) {
            int hz = idx / 340, r = idx - hz * 340;
            int hy = r / 34,   hx = r - hy * 34;
            int gz = z0 - 1 + hz, gy = y0 - 1 + hy, gx = hx - 1;
            float v = 0.f;
            if ((unsigned)gz < 32u && (unsigned)gy < 32u && (unsigned)gx < 32u)
                v = src[gz * 1024 + gy * 32 + gx];
            halo[idx] = v;
        }
    }

    int p = 0;
    for (int step = 0; step < 24; step++) {
        const int phase = step >> 3, cl = step & 7;
        __syncthreads();   // halo[p] ready; previous wpart reads done

        // ---- prefetch step+1 halo into registers (stores after compute) ----
        float pf[14];
        if (step + 1 < 24) {
            const int np = (step + 1) >> 3, ncl = (step + 1) & 7;
            const int ngch = (np == 0 ? 64 : np == 1 ? 128 : 0) + h * 8 + ncl;
            const float* src = g_qkv_pre + ((size_t)(b * 192 + ngch)) * SPT;
            #pragma unroll
            for (int i = 0; i < 14; i++) {
                int idx = tid + i * 256;
                float v = 0.f;
                if (idx < 3400) {
                    int hz = idx / 340, r = idx - hz * 340;
                    int hy = r / 34,   hx = r - hy * 34;
                    int gz = z0 - 1 + hz, gy = y0 - 1 + hy, gx = hx - 1;
                    if ((unsigned)gz < 32u && (unsigned)gy < 32u && (unsigned)gx < 32u)
                        v = src[gz * 1024 + gy * 32 + gx];
                }
                pf[i] = v;
            }
        }

        // ---- compute current step from halo[p] ----
        const float* hb = halo + p * 3400;
        float wr[27];
        #pragma unroll
        for (int t = 0; t < 27; t++) wr[t] = wall[step * 27 + t];

        float pa[9], pb[9], pc[9];
        #pragma unroll
        for (int e = 0; e < 9; e++) {
            int dy = e / 3, dx = e % 3;
            pa[e] = hb[0 * 340 + (ly + dy) * 34 + lx + dx];
            pb[e] = hb[1 * 340 + (ly + dy) * 34 + lx + dx];
        }

        float qn_l = 0.f, kn_l = 0.f, gl[8];
        #pragma unroll
        for (int d = 0; d < 8; d++) gl[d] = 0.f;

        #pragma unroll
        for (int lz = 0; lz < 8; lz++) {
            #pragma unroll
            for (int e = 0; e < 9; e++) {
                int dy = e / 3, dx = e % 3;
                pc[e] = hb[(lz + 2) * 340 + (ly + dy) * 34 + lx + dx];
            }
            float val = 0.f;
            #pragma unroll
            for (int e = 0; e < 9; e++) val = fmaf(wr[e],      pa[e], val);
            #pragma unroll
            for (int e = 0; e < 9; e++) val = fmaf(wr[9 + e],  pb[e], val);
            #pragma unroll
            for (int e = 0; e < 9; e++) val = fmaf(wr[18 + e], pc[e], val);

            const int pp = lz * 256 + tid;
            if (phase == 0) {
                ks[cl * 2048 + pp] = val;
                kn_l = fmaf(val, val, kn_l);
            } else if (phase == 1) {
                g_v[((size_t)(b * 64 + h * 8 + cl)) * SPT
                    + (z0 + lz) * 1024 + (y0 + ly) * 32 + lx] = val;
            } else {
                qn_l = fmaf(val, val, qn_l);
                #pragma unroll
                for (int d = 0; d < 8; d++)
                    gl[d] = fmaf(val, ks[d * 2048 + pp], gl[d]);
            }
            #pragma unroll
            for (int e = 0; e < 9; e++) { pa[e] = pb[e]; pb[e] = pc[e]; }
        }

        // ---- store prefetched halo into the other buffer ----
        if (step + 1 < 24) {
            float* nb = halo + (1 - p) * 3400;
            #pragma unroll
            for (int i = 0; i < 14; i++) {
                int idx = tid + i * 256;
                if (idx < 3400) nb[idx] = pf[i];
            }
        }

        // ---- deterministic reductions ----
        if (phase == 0) {
            #pragma unroll
            for (int o = 16; o; o >>= 1) kn_l += __shfl_xor_sync(0xffffffffu, kn_l, o);
            if (lane == 0) wpart[warp * 9] = kn_l;
        } else if (phase == 2) {
            #pragma unroll
            for (int d = 0; d < 8; d++) {
                float v = gl[d];
                #pragma unroll
                for (int o = 16; o; o >>= 1) v += __shfl_xor_sync(0xffffffffu, v, o);
                if (lane == 0) wpart[warp * 9 + d] = v;
            }
            #pragma unroll
            for (int o = 16; o; o >>= 1) qn_l += __shfl_xor_sync(0xffffffffu, qn_l, o);
            if (lane == 0) wpart[warp * 9 + 8] = qn_l;
        }
        __syncthreads();

        if (phase == 0) {
            if (tid == 0) {
                float s = 0.f;
                #pragma unroll
                for (int w = 0; w < 8; w++) s += wpart[w * 9];
                knacc[cl] += s;
            }
        } else if (phase == 2) {
            if (tid < 9) {
                float s = 0.f;
                #pragma unroll
                for (int w = 0; w < 8; w++) s += wpart[w * 9 + tid];
                if (tid < 8) gacc[cl * 8 + tid] += s;
                else         qnacc[cl] += s;
            }
        }
        p ^= 1;
    }
    __syncthreads();
    if (tid < 80) {
        float v = tid < 64 ? gacc[tid] : tid < 72 ? qnacc[tid - 64] : knacc[tid - 72];
        g_partials[(((size_t)(b * 8 + h)) * 16 + blockIdx.x) * 80 + tid] = v;
    }
}

// ---------------------------------------------------------------------------
// Tiny kernel: reduce tile partials -> L2-normalized gram -> softmax -> fold
// with w_proj into M[b][o][h*8+d].
// ---------------------------------------------------------------------------
__global__ void attn_kernel(const float* __restrict__ temp,
                            const float* __restrict__ w_proj)
{
    __shared__ float stat_s[8][80];   // per head: 64 gram, 8 qn2, 8 kn2
    __shared__ float attn_s[8][8][8]; // [h][c][d]
    const int b = blockIdx.x, tid = threadIdx.x;

    for (int idx = tid; idx < 640; idx += 256) {
        int h = idx / 80, j = idx - h * 80;
        float s = 0.f;
        #pragma unroll
        for (int t = 0; t < 16; t++)
            s += g_partials[(((size_t)(b * 8 + h)) * 16 + t) * 80 + j];
        stat_s[h][j] = s;
    }
    __syncthreads();

    if (tid < 64) {
        const int h = tid >> 3, c = tid & 7;
        const float qn = fmaxf(sqrtf(stat_s[h][64 + c]), 1e-12f);
        const float tmp = temp[b];
        float g[8]; float mx = -1e30f;
        #pragma unroll
        for (int d = 0; d < 8; d++) {
            float kn = fmaxf(sqrtf(stat_s[h][72 + d]), 1e-12f);
            g[d] = stat_s[h][c * 8 + d] / (qn * kn) * tmp;
            mx = fmaxf(mx, g[d]);
        }
        float ssum = 0.f;
        #pragma unroll
        for (int d = 0; d < 8; d++) { g[d] = expf(g[d] - mx); ssum += g[d]; }
        const float inv = 1.f / ssum;
        #pragma unroll
        for (int d = 0; d < 8; d++) attn_s[h][c][d] = g[d] * inv;
    }
    __syncthreads();

    for (int e = tid; e < 4096; e += 256) {
        int o = e >> 6, j = e & 63, h = j >> 3, d = j & 7;
        float m = 0.f;
        #pragma unroll
        for (int c = 0; c < 8; c++)
            m = fmaf(w_proj[o * 64 + h * 8 + c], attn_s[h][c][d], m);
        g_M[b * 4096 + e] = m;
    }
}

// ---------------------------------------------------------------------------
extern "C" void kernel_launch(void* const* d_in, const int* in_sizes, int n_in,
                              void* d_out, int out_size)
{
    const float* x      = (const float*)d_in[0];
    const float* w_qkv  = (const float*)d_in[1];
    const float* w_dw   = (const float*)d_in[2];
    const float* w_proj = (const float*)d_in[3];
    const float* temp   = (const float*)d_in[4];
    float* out = (float*)d_out;

    void *p_qkv, *p_v, *p_M;
    cudaGetSymbolAddress(&p_qkv, g_qkv_pre);
    cudaGetSymbolAddress(&p_v,   g_v);
    cudaGetSymbolAddress(&p_M,   g_M);

    const int gemm_smem = (4096 + 8192) * 4;    // 48 KiB
    const int dw_smem   = 23984 * 4;            // ~93.7 KiB
    cudaFuncSetAttribute(gemm_kernel<false>, cudaFuncAttributeMaxDynamicSharedMemorySize, gemm_smem);
    cudaFuncSetAttribute(gemm_kernel<true>,  cudaFuncAttributeMaxDynamicSharedMemorySize, gemm_smem);
    cudaFuncSetAttribute(dw_kernel,          cudaFuncAttributeMaxDynamicSharedMemorySize, dw_smem);

    // K1: qkv pointwise conv (per-batch GEMM, A shared)
    gemm_kernel<false><<<dim3(3, 256, 8), 256, gemm_smem>>>(w_qkv, x, (float*)p_qkv, 192);
    // K2: depthwise conv + gram/norm partials + v
    dw_kernel<<<dim3(16, 8, 8), 256, dw_smem>>>(w_dw);
    // K3: softmax + fold attn with w_proj into per-batch 64x64 M
    attn_kernel<<<8, 256>>>(temp, w_proj);
    // K4: y = M * v, writes d_out (per-batch A)
    gemm_kernel<true><<<dim3(1, 256, 8), 256, gemm_smem>>>((const float*)p_M, (const float*)p_v, out, 64);
}

// round 5
// speedup vs baseline: 1.7670x; 1.2851x over previous
#include <cuda_runtime.h>
#include <math.h>

// Problem constants
#define BB   8
#define SPT  32768          // 32*32*32
#define NHEADS 8

// ---------------- scratch (device globals: allocation-free) ----------------
__device__ float g_qkv_pre[(size_t)BB * 192 * SPT];   // 192 MiB
__device__ float g_v[(size_t)BB * 64 * SPT];          //  64 MiB
__device__ float g_partials[BB * NHEADS * 16 * 80];   // per-tile gram/norm partials
__device__ float g_M[BB * 64 * 64];                   // folded attn+proj matrices

// ---------------- f32x2 packed helpers ----------------
__device__ __forceinline__ void fma2(unsigned long long& d,
                                     unsigned long long a,
                                     unsigned long long b) {
    asm("fma.rn.f32x2 %0, %1, %2, %0;" : "+l"(d) : "l"(a), "l"(b));
}
__device__ __forceinline__ unsigned long long pk2(float x) {
    unsigned long long r;
    asm("mov.b64 %0, {%1, %1};" : "=l"(r) : "f"(x));
    return r;
}
__device__ __forceinline__ float2 upk(unsigned long long v) {
    float lo, hi;
    asm("mov.b64 {%0, %1}, %2;" : "=f"(lo), "=f"(hi) : "l"(v));
    return make_float2(lo, hi);
}

// ---------------------------------------------------------------------------
// GEMM: C[b][ocb+oc][s] = A[oc][k=64] * X[b][k][s].
// S tile 128, 256 threads, 8 oc x 4 s per thread (acc as 8x2 f32x2 pairs).
// As transposed [k][oc] (pad 68) -> a loads are 2x LDS.128 broadcast.
// Inner loop: 3 LDS + 8 MOV + 16 FFMA2 per k.
// OCG: oc-groups computed per block reusing the X tile (K1=3, K4=1).
// ---------------------------------------------------------------------------
template<int OCG, bool APB>
__global__ __launch_bounds__(256, 4)
void gemm_kernel(const float* __restrict__ A,
                 const float* __restrict__ X,
                 float* __restrict__ C, int OCtot)
{
    extern __shared__ float sm[];
    float* As = sm;                       // [64][68] transposed, 17408 B
    float* Xs = sm + 4352;                // [64][128] floats, 32768 B

    const int tid = threadIdx.x;
    const int b   = blockIdx.z;
    const int s0  = blockIdx.y * 128;
    const int warp = tid >> 5, lane = tid & 31;

    // load X tile once: 2048 float4s
    const float* Xb = X + (size_t)b * 64 * SPT + s0;
    #pragma unroll
    for (int i = 0; i < 8; i++) {
        int e = tid + i * 256;
        int row = e >> 5, c4 = e & 31;
        ((float4*)Xs)[e] = ((const float4*)(Xb + (size_t)row * SPT))[c4];
    }

    const float* Abase = A + (APB ? (size_t)b * OCtot * 64 : (size_t)0);

    #pragma unroll
    for (int g = 0; g < OCG; g++) {
        const int ocb = g * 64;
        if (g) __syncthreads();           // protect As reuse
        // load As transposed: i -> k = i&63, oc = i>>6 per 256-thread stripe
        #pragma unroll
        for (int it = 0; it < 16; it++) {
            int i = tid + it * 256;
            int k = i & 63, oc = i >> 6;
            As[k * 68 + oc] = Abase[(size_t)(ocb + oc) * 64 + k];
        }
        __syncthreads();

        unsigned long long acc[8][2];
        #pragma unroll
        for (int i = 0; i < 8; i++) { acc[i][0] = 0ull; acc[i][1] = 0ull; }

        #pragma unroll 4
        for (int k = 0; k < 64; k++) {
            float4 a0 = *(const float4*)&As[k * 68 + warp * 8];
            float4 a1 = *(const float4*)&As[k * 68 + warp * 8 + 4];
            ulonglong2 xv = *(const ulonglong2*)&Xs[k * 128 + lane * 4];
            float av[8] = {a0.x, a0.y, a0.z, a0.w, a1.x, a1.y, a1.z, a1.w};
            #pragma unroll
            for (int i = 0; i < 8; i++) {
                unsigned long long aa = pk2(av[i]);
                fma2(acc[i][0], aa, xv.x);
                fma2(acc[i][1], aa, xv.y);
            }
        }

        #pragma unroll
        for (int i = 0; i < 8; i++) {
            float2 lo = upk(acc[i][0]);
            float2 hi = upk(acc[i][1]);
            float* Crow = C + ((size_t)b * OCtot + ocb + warp * 8 + i) * SPT
                            + s0 + lane * 4;
            *((float4*)Crow) = make_float4(lo.x, lo.y, hi.x, hi.y);
        }
    }
}

// ---------------------------------------------------------------------------
// Depthwise 3x3x3 conv + fused gram/norm partials + v store.
// Double-buffered halo: step s prefetches step s+1's halo (reg-staged LDG,
// STS after compute) so global latency overlaps the conv FMA body.
// All reductions fixed-order (deterministic).
// ---------------------------------------------------------------------------
__global__ __launch_bounds__(256, 2)
void dw_kernel(const float* __restrict__ w_dw)
{
    extern __shared__ float sm[];
    float* halo  = sm;               // 2 * 3400
    float* ks    = sm + 6800;        // 8*2048 = 16384
    float* gacc  = ks + 16384;       // 64
    float* qnacc = gacc + 64;        // 8
    float* knacc = qnacc + 8;        // 8
    float* wall  = knacc + 8;        // 24*27 = 648
    float* wpart = wall + 648;       // 8 warps * 9 slots = 72
    // total 23984 floats = ~93.7 KiB

    const int tid = threadIdx.x;
    const int b = blockIdx.z, h = blockIdx.y;
    const int z0 = (blockIdx.x >> 2) * 8;
    const int y0 = (blockIdx.x & 3) * 8;
    const int ly = tid >> 5, lx = tid & 31;
    const int warp = ly, lane = lx;

    if (tid < 64) gacc[tid] = 0.f;
    else if (tid < 72) qnacc[tid - 64] = 0.f;
    else if (tid < 80) knacc[tid - 72] = 0.f;

    // preload all 24 channels' weights (step order: k ch 0-7, v 0-7, q 0-7)
    for (int i = tid; i < 648; i += 256) {
        int step = i / 27, t = i - step * 27;
        int phase = step >> 3, cl = step & 7;
        int gch = (phase == 0 ? 64 : phase == 1 ? 128 : 0) + h * 8 + cl;
        wall[i] = w_dw[gch * 27 + t];
    }

    // prologue: halo for step 0 (k channel 0)
    {
        const float* src = g_qkv_pre + ((size_t)(b * 192 + 64 + h * 8)) * SPT;
        for (int idx = tid; idx < 3400; idx += 256) {
            int hz = idx / 340, r = idx - hz * 340;
            int hy = r / 34,   hx = r - hy * 34;
            int gz = z0 - 1 + hz, gy = y0 - 1 + hy, gx = hx - 1;
            float v = 0.f;
            if ((unsigned)gz < 32u && (unsigned)gy < 32u && (unsigned)gx < 32u)
                v = src[gz * 1024 + gy * 32 + gx];
            halo[idx] = v;
        }
    }

    int p = 0;
    for (int step = 0; step < 24; step++) {
        const int phase = step >> 3, cl = step & 7;
        __syncthreads();   // halo[p] ready; previous wpart reads done

        // ---- prefetch step+1 halo into registers (stores after compute) ----
        float pf[14];
        if (step + 1 < 24) {
            const int np = (step + 1) >> 3, ncl = (step + 1) & 7;
            const int ngch = (np == 0 ? 64 : np == 1 ? 128 : 0) + h * 8 + ncl;
            const float* src = g_qkv_pre + ((size_t)(b * 192 + ngch)) * SPT;
            #pragma unroll
            for (int i = 0; i < 14; i++) {
                int idx = tid + i * 256;
                float v = 0.f;
                if (idx < 3400) {
                    int hz = idx / 340, r = idx - hz * 340;
                    int hy = r / 34,   hx = r - hy * 34;
                    int gz = z0 - 1 + hz, gy = y0 - 1 + hy, gx = hx - 1;
                    if ((unsigned)gz < 32u && (unsigned)gy < 32u && (unsigned)gx < 32u)
                        v = src[gz * 1024 + gy * 32 + gx];
                }
                pf[i] = v;
            }
        }

        // ---- compute current step from halo[p] ----
        const float* hb = halo + p * 3400;
        float wr[27];
        #pragma unroll
        for (int t = 0; t < 27; t++) wr[t] = wall[step * 27 + t];

        float pa[9], pb[9], pc[9];
        #pragma unroll
        for (int e = 0; e < 9; e++) {
            int dy = e / 3, dx = e % 3;
            pa[e] = hb[0 * 340 + (ly + dy) * 34 + lx + dx];
            pb[e] = hb[1 * 340 + (ly + dy) * 34 + lx + dx];
        }

        float qn_l = 0.f, kn_l = 0.f, gl[8];
        #pragma unroll
        for (int d = 0; d < 8; d++) gl[d] = 0.f;

        #pragma unroll
        for (int lz = 0; lz < 8; lz++) {
            #pragma unroll
            for (int e = 0; e < 9; e++) {
                int dy = e / 3, dx = e % 3;
                pc[e] = hb[(lz + 2) * 340 + (ly + dy) * 34 + lx + dx];
            }
            float val = 0.f;
            #pragma unroll
            for (int e = 0; e < 9; e++) val = fmaf(wr[e],      pa[e], val);
            #pragma unroll
            for (int e = 0; e < 9; e++) val = fmaf(wr[9 + e],  pb[e], val);
            #pragma unroll
            for (int e = 0; e < 9; e++) val = fmaf(wr[18 + e], pc[e], val);

            const int pp = lz * 256 + tid;
            if (phase == 0) {
                ks[cl * 2048 + pp] = val;
                kn_l = fmaf(val, val, kn_l);
            } else if (phase == 1) {
                g_v[((size_t)(b * 64 + h * 8 + cl)) * SPT
                    + (z0 + lz) * 1024 + (y0 + ly) * 32 + lx] = val;
            } else {
                qn_l = fmaf(val, val, qn_l);
                #pragma unroll
                for (int d = 0; d < 8; d++)
                    gl[d] = fmaf(val, ks[d * 2048 + pp], gl[d]);
            }
            #pragma unroll
            for (int e = 0; e < 9; e++) { pa[e] = pb[e]; pb[e] = pc[e]; }
        }

        // ---- store prefetched halo into the other buffer ----
        if (step + 1 < 24) {
            float* nb = halo + (1 - p) * 3400;
            #pragma unroll
            for (int i = 0; i < 14; i++) {
                int idx = tid + i * 256;
                if (idx < 3400) nb[idx] = pf[i];
            }
        }

        // ---- deterministic reductions ----
        if (phase == 0) {
            #pragma unroll
            for (int o = 16; o; o >>= 1) kn_l += __shfl_xor_sync(0xffffffffu, kn_l, o);
            if (lane == 0) wpart[warp * 9] = kn_l;
        } else if (phase == 2) {
            #pragma unroll
            for (int d = 0; d < 8; d++) {
                float v = gl[d];
                #pragma unroll
                for (int o = 16; o; o >>= 1) v += __shfl_xor_sync(0xffffffffu, v, o);
                if (lane == 0) wpart[warp * 9 + d] = v;
            }
            #pragma unroll
            for (int o = 16; o; o >>= 1) qn_l += __shfl_xor_sync(0xffffffffu, qn_l, o);
            if (lane == 0) wpart[warp * 9 + 8] = qn_l;
        }
        __syncthreads();

        if (phase == 0) {
            if (tid == 0) {
                float s = 0.f;
                #pragma unroll
                for (int w = 0; w < 8; w++) s += wpart[w * 9];
                knacc[cl] += s;
            }
        } else if (phase == 2) {
            if (tid < 9) {
                float s = 0.f;
                #pragma unroll
                for (int w = 0; w < 8; w++) s += wpart[w * 9 + tid];
                if (tid < 8) gacc[cl * 8 + tid] += s;
                else         qnacc[cl] += s;
            }
        }
        p ^= 1;
    }
    __syncthreads();
    if (tid < 80) {
        float v = tid < 64 ? gacc[tid] : tid < 72 ? qnacc[tid - 64] : knacc[tid - 72];
        g_partials[(((size_t)(b * 8 + h)) * 16 + blockIdx.x) * 80 + tid] = v;
    }
}

// ---------------------------------------------------------------------------
// Tiny kernel: reduce tile partials -> L2-normalized gram -> softmax -> fold
// with w_proj into M[b][o][h*8+d].
// ---------------------------------------------------------------------------
__global__ void attn_kernel(const float* __restrict__ temp,
                            const float* __restrict__ w_proj)
{
    __shared__ float stat_s[8][80];   // per head: 64 gram, 8 qn2, 8 kn2
    __shared__ float attn_s[8][8][8]; // [h][c][d]
    const int b = blockIdx.x, tid = threadIdx.x;

    for (int idx = tid; idx < 640; idx += 256) {
        int h = idx / 80, j = idx - h * 80;
        float s = 0.f;
        #pragma unroll
        for (int t = 0; t < 16; t++)
            s += g_partials[(((size_t)(b * 8 + h)) * 16 + t) * 80 + j];
        stat_s[h][j] = s;
    }
    __syncthreads();

    if (tid < 64) {
        const int h = tid >> 3, c = tid & 7;
        const float qn = fmaxf(sqrtf(stat_s[h][64 + c]), 1e-12f);
        const float tmp = temp[b];
        float g[8]; float mx = -1e30f;
        #pragma unroll
        for (int d = 0; d < 8; d++) {
            float kn = fmaxf(sqrtf(stat_s[h][72 + d]), 1e-12f);
            g[d] = stat_s[h][c * 8 + d] / (qn * kn) * tmp;
            mx = fmaxf(mx, g[d]);
        }
        float ssum = 0.f;
        #pragma unroll
        for (int d = 0; d < 8; d++) { g[d] = expf(g[d] - mx); ssum += g[d]; }
        const float inv = 1.f / ssum;
        #pragma unroll
        for (int d = 0; d < 8; d++) attn_s[h][c][d] = g[d] * inv;
    }
    __syncthreads();

    for (int e = tid; e < 4096; e += 256) {
        int o = e >> 6, j = e & 63, h = j >> 3, d = j & 7;
        float m = 0.f;
        #pragma unroll
        for (int c = 0; c < 8; c++)
            m = fmaf(w_proj[o * 64 + h * 8 + c], attn_s[h][c][d], m);
        g_M[b * 4096 + e] = m;
    }
}

// ---------------------------------------------------------------------------
extern "C" void kernel_launch(void* const* d_in, const int* in_sizes, int n_in,
                              void* d_out, int out_size)
{
    const float* x      = (const float*)d_in[0];
    const float* w_qkv  = (const float*)d_in[1];
    const float* w_dw   = (const float*)d_in[2];
    const float* w_proj = (const float*)d_in[3];
    const float* temp   = (const float*)d_in[4];
    float* out = (float*)d_out;

    void *p_qkv, *p_v, *p_M;
    cudaGetSymbolAddress(&p_qkv, g_qkv_pre);
    cudaGetSymbolAddress(&p_v,   g_v);
    cudaGetSymbolAddress(&p_M,   g_M);

    const int gemm_smem = (4352 + 8192) * 4;    // 50176 B
    const int dw_smem   = 23984 * 4;            // ~93.7 KiB
    cudaFuncSetAttribute((const void*)gemm_kernel<3, false>, cudaFuncAttributeMaxDynamicSharedMemorySize, gemm_smem);
    cudaFuncSetAttribute((const void*)gemm_kernel<1, true>,  cudaFuncAttributeMaxDynamicSharedMemorySize, gemm_smem);
    cudaFuncSetAttribute((const void*)dw_kernel,             cudaFuncAttributeMaxDynamicSharedMemorySize, dw_smem);

    // K1: qkv pointwise conv (per-batch GEMM, X tile reused across 3 oc-groups)
    gemm_kernel<3, false><<<dim3(1, 256, 8), 256, gemm_smem>>>(w_qkv, x, (float*)p_qkv, 192);
    // K2: depthwise conv + gram/norm partials + v
    dw_kernel<<<dim3(16, 8, 8), 256, dw_smem>>>(w_dw);
    // K3: softmax + fold attn with w_proj into per-batch 64x64 M
    attn_kernel<<<8, 256>>>(temp, w_proj);
    // K4: y = M * v, writes d_out (per-batch A)
    gemm_kernel<1, true><<<dim3(1, 256, 8), 256, gemm_smem>>>((const float*)p_M, (const float*)p_v, out, 64);
}